// round 9
// baseline (speedup 1.0000x reference)
#include <cuda_runtime.h>

// FeatureExtractor_50165218017745  (R9: TMA-bulk staged, bypass L1tex path)
// Input : imgs_in [64, 3, 512, 512] float32 in [0,1)
// Output: [64, 96, 4, 4] float32
//
// Loads go through the TMA engine (cp.async.bulk -> UBLKCP), not LDG/LDGSTS,
// to test/bypass the suspected per-SM L1tex outstanding-request cap that has
// pinned DRAM at ~68% across 4 prior designs. 2-slot x 4KB smem ring (2 full
// 2KB rows per slot), mbarrier complete_tx, tid0 producer. Each thread
// consumes ONE float4 per slot; its quadrant parity is fixed: q=(tid>>6)&1.
// u8 parity-packed privatized hist (bank==lane, conflict-free, max 192<255).
// 16K hist + 8K stage, 8 CTAs/SM, 1024 blocks = ONE wave.
// Fused threadfence-reduction epilogue + scratch reset for graph replay.

#define BINS   32
#define BATCH  64
#define NBLK   1024   // 64 b * 2 qy * 8 part

__device__ unsigned g_counts[BATCH * 4 * BINS];  // zero-init; reset each run
__device__ unsigned g_done[BATCH];               // zero-init; reset each run

__device__ __forceinline__ void mbar_init(unsigned mbar, unsigned cnt) {
    asm volatile("mbarrier.init.shared.b64 [%0], %1;" :: "r"(mbar), "r"(cnt) : "memory");
}
__device__ __forceinline__ void mbar_expect_tx(unsigned mbar, unsigned bytes) {
    asm volatile("mbarrier.arrive.expect_tx.shared.b64 _, [%0], %1;"
                 :: "r"(mbar), "r"(bytes) : "memory");
}
__device__ __forceinline__ void tma_bulk_g2s(unsigned dst, const void* src,
                                             unsigned bytes, unsigned mbar) {
    asm volatile("cp.async.bulk.shared::cta.global.mbarrier::complete_tx::bytes "
                 "[%0], [%1], %2, [%3];"
                 :: "r"(dst), "l"(src), "r"(bytes), "r"(mbar) : "memory");
}
__device__ __forceinline__ void mbar_wait(unsigned mbar, unsigned phase) {
    asm volatile(
        "{\n\t.reg .pred P;\n\t"
        "W%=:\n\t"
        "mbarrier.try_wait.parity.acquire.cta.shared::cta.b64 P, [%0], %1, 0x989680;\n\t"
        "@!P bra W%=;\n\t}"
        :: "r"(mbar), "r"(phase) : "memory");
}

// bin = floor(32x) for x in [0,1): FFMA.RZ + 2^23 leaves floor(32x) in the
// low mantissa bits (exact for 0 <= 32x < 2^23).
__device__ __forceinline__ unsigned bin_of(float x) {
    return __float_as_uint(__fmaf_rz(x, 32.0f, 8388608.0f)) & 31u;
}

__device__ __forceinline__ void bump4(const float4& a, unsigned char* __restrict__ h) {
    h[bin_of(a.x) << 9] += 1u;
    h[bin_of(a.y) << 9] += 1u;
    h[bin_of(a.z) << 9] += 1u;
    h[bin_of(a.w) << 9] += 1u;
}

__global__ __launch_bounds__(256, 8)
void fused_kernel(const float* __restrict__ in, float* __restrict__ out) {
    __shared__ unsigned char hist8[BINS * 512];       // 16 KB
    __shared__ __align__(16) float4 stage[2][256];    // 8 KB: 2 slots x 2 rows
    __shared__ __align__(8) unsigned long long mbars[2];

    int bid  = blockIdx.x;                  // ((b*2 + qy)*8 + part)
    int part = bid & 7;
    int qy   = (bid >> 3) & 1;
    int b    = bid >> 4;

    int tid  = threadIdx.x;
    int warp = tid >> 5;
    int lane = tid & 31;

    unsigned mb = (unsigned)__cvta_generic_to_shared(&mbars[0]);
    unsigned st = (unsigned)__cvta_generic_to_shared(&stage[0][0]);

    // chunk j (0..47) = rows [part*96 + 2j, +2) of region (b, qy)
    const float* rbase = in + (size_t)b * 786432 + (size_t)qy * 131072;
    auto chunk_src = [&](int j) -> const float* {
        int ridx = part * 96 + 2 * j;       // region row 0..767 (pair-aligned)
        return rbase + ((ridx >> 8) * 262144) + ((ridx & 255) * 512);
    };

    if (tid == 0) {
        mbar_init(mb, 1u);
        mbar_init(mb + 8, 1u);
    }

    // zero histograms (4096 u32 words / 256 threads = 4 uint4 each)
    {
        uint4* z = (uint4*)hist8;
        #pragma unroll
        for (int i = 0; i < 4; i++)
            z[tid + 256 * i] = make_uint4(0u, 0u, 0u, 0u);
    }
    __syncthreads();                        // mbar init + hist zero visible

    if (tid == 0) {
        mbar_expect_tx(mb, 4096u);
        tma_bulk_g2s(st, chunk_src(0), 4096u, mb);
        mbar_expect_tx(mb + 8, 4096u);
        tma_bulk_g2s(st + 4096, chunk_src(1), 4096u, mb + 8);
    }

    // Per-thread u8 slot (R8 packing): byte = bin*512 + (warp>>1)*128 +
    // lane*4 + (warp&1)*2 + q, with q = (tid>>6)&1 fixed per thread; unused
    // bytes stay zero so the dp4a reduction below is unchanged.
    unsigned char* hq = hist8 + ((warp >> 1) << 7) + (lane << 2)
                              + ((warp & 1) << 1) + ((tid >> 6) & 1);

    #pragma unroll 1
    for (int k = 0; k < 48; k++) {
        int s = k & 1;
        mbar_wait(mb + s * 8, (k >> 1) & 1);
        float4 v = stage[s][tid];
        __syncthreads();                    // all reads done before slot reuse
        if (k < 46 && tid == 0) {
            mbar_expect_tx(mb + s * 8, 4096u);
            tma_bulk_g2s(st + s * 4096, chunk_src(k + 2), 4096u, mb + s * 8);
        }
        bump4(v, hq);                       // RMW hidden under next TMA
    }
    __syncthreads();

    // Reduction (dp4a byte masks): bytes 0,2 -> q0, bytes 1,3 -> q1.
    unsigned* scratch = (unsigned*)&stage[0][0];   // stage now free (2052 B)
    {
        unsigned acc0 = 0, acc1 = 0;
        int bin = tid & 31, grp = tid >> 5;
        const unsigned* hw = (const unsigned*)hist8;
        int base = bin * 128 + grp * 16;
        #pragma unroll
        for (int i = 0; i < 16; i++) {
            unsigned w = hw[base + ((i + bin) & 15)];
            acc0 = __dp4a(w, 0x00010001u, acc0);
            acc1 = __dp4a(w, 0x01000100u, acc1);
        }
        scratch[tid] = acc0;
        scratch[256 + tid] = acc1;
    }
    __syncthreads();
    if (tid < 64) {
        int q = tid >> 5, bn = tid & 31;
        unsigned tot = 0;
        #pragma unroll
        for (int c = 0; c < 8; c++)
            tot += scratch[q * 256 + c * 32 + bn];
        atomicAdd(&g_counts[((b << 2) + (qy << 1) + q) * BINS + bn], tot);
    }

    // Release counts, then bump per-batch arrival counter (16 blocks/batch).
    __threadfence();
    __syncthreads();
    if (tid == 0)
        scratch[512] = atomicAdd(&g_done[b], 1u);
    __syncthreads();
    unsigned rank = scratch[512];
    if (rank != 15u) return;                // not the last block of batch b

    // ---- last block of batch b: finalize (overlapped with other batches) ----
    __threadfence();                        // acquire
    __syncthreads();

    float* s1  = (float*)hist8;             // [128]: per-quadrant hist / 65536
    float* s0v = ((float*)hist8) + 128;     // [32] : full-image hist / 262144

    if (tid < 128) {
        unsigned c = __ldcg(&g_counts[(b << 7) + tid]);
        s1[tid] = (float)c * (1.0f / 65536.0f);
        g_counts[(b << 7) + tid] = 0u;      // reset for next replay
    }
    __syncthreads();
    if (tid < 32)
        s0v[tid] = (s1[tid] + s1[32 + tid] + s1[64 + tid] + s1[96 + tid]) * 0.25f;
    if (tid == 0)
        g_done[b] = 0u;                     // reset for next replay
    __syncthreads();

    #pragma unroll
    for (int k = 0; k < 6; k++) {
        int idx  = tid + 256 * k;           // 0..1535
        int ch   = idx >> 4;
        int cell = idx & 15;                // y*4 + x
        float v = 0.0f;
        if (ch < 32) {
            v = s0v[ch];
        } else if (ch < 64) {
            int qq = ((cell >> 3) << 1) | ((cell >> 1) & 1);  // (y>>1)*2+(x>>1)
            v = s1[qq * BINS + (ch - 32)];
        }
        out[b * 1536 + idx] = v;
    }
}

extern "C" void kernel_launch(void* const* d_in, const int* in_sizes, int n_in,
                              void* d_out, int out_size) {
    (void)in_sizes; (void)n_in; (void)out_size;
    fused_kernel<<<NBLK, 256>>>((const float*)d_in[0], (float*)d_out);
}

// round 10
// speedup vs baseline: 1.0065x; 1.0065x over previous
#include <cuda_runtime.h>

// FeatureExtractor_50165218017745  (R10: 8 CTA/SM, fine-grain blocks, __ldcs)
// Input : imgs_in [64, 3, 512, 512] float32 in [0,1)
// Output: [64, 96, 4, 4] float32
//
// R5 base (parity-packed u16 privatized smem hist, bank == lane, depth-1
// LDG.128 prefetch) with the last untried knobs: 2048 threads/SM
// (launch_bounds(256,8), regs=32), 2048 half-size blocks for fine-grained
// tail balancing, and evict-first streaming loads (__ldcs) since the input
// has zero reuse. Fused threadfence-reduction epilogue + replay reset.

#define BINS   32
#define BATCH  64
#define PARTS  8
#define NBLK   (BATCH * 4 * PARTS)   // 2048 blocks

__device__ unsigned g_counts[BATCH * 4 * BINS];  // zero-init; reset each run
__device__ unsigned g_done[BATCH];               // zero-init; reset each run

// bin = floor(32x) for x in [0,1): FFMA.RZ + 2^23 leaves floor(32x) in the
// low mantissa bits (exact for 0 <= 32x < 2^23).
__device__ __forceinline__ unsigned bin_of(float x) {
    return __float_as_uint(__fmaf_rz(x, 32.0f, 8388608.0f)) & 31u;
}

__device__ __forceinline__ void bump8(const float4& a, const float4& b,
                                      unsigned short* __restrict__ h) {
    h[bin_of(a.x) << 8] += 1u;
    h[bin_of(a.y) << 8] += 1u;
    h[bin_of(a.z) << 8] += 1u;
    h[bin_of(a.w) << 8] += 1u;
    h[bin_of(b.x) << 8] += 1u;
    h[bin_of(b.y) << 8] += 1u;
    h[bin_of(b.z) << 8] += 1u;
    h[bin_of(b.w) << 8] += 1u;
}

__device__ __forceinline__ const float4* row_ptr(const float* __restrict__ in,
                                                 int b, int qy, int qx, int ridx) {
    int c = ridx >> 8;        // channel 0..2
    int r = ridx & 255;       // row within quadrant
    return (const float4*)(in + (((((b * 3 + c) << 9) + (qy << 8) + r) << 9) + (qx << 8)));
}

__global__ __launch_bounds__(256, 8)
void fused_kernel(const float* __restrict__ in, float* __restrict__ out) {
    __shared__ unsigned short hist[BINS * 256];   // 16 KB: parity-packed
    __shared__ unsigned scratch[256 + 1];

    int bid  = blockIdx.x;                  // ((b*4 + q) * PARTS + part)
    int part = bid & (PARTS - 1);
    int q    = (bid >> 3) & 3;
    int b    = bid >> 5;
    int qy   = q >> 1;
    int qx   = q & 1;

    int tid  = threadIdx.x;
    int warp = tid >> 5;
    int lane = tid & 31;

    // zero private histograms (4096 u32 words / 256 threads = 4 uint4 each)
    {
        uint4* z = (uint4*)hist;
        #pragma unroll
        for (int i = 0; i < 4; i++)
            z[tid + 256 * i] = make_uint4(0u, 0u, 0u, 0u);
    }
    __syncthreads();

    // Parity-packed slot: byte = bin*512 + (warp>>1)*128 + lane*4 + (warp&1)*2
    // -> bank = lane for every bin; bin b's 256 counters occupy u16 range
    // [b*256, b*256+256) (permuted), so the reduction is layout-agnostic.
    unsigned short* h = hist + ((warp >> 1) << 6) + (lane << 1) + (warp & 1);

    // 768 quadrant-rows (3 ch x 256); 64 warp-stripes -> 12 rows/warp.
    // Depth-1 prefetch, evict-first streaming loads (zero reuse).
    int ridx = part * 8 + warp;             // 0..63
    const float4* p = row_ptr(in, b, qy, qx, ridx);
    float4 v0 = __ldcs(p + lane);
    float4 v1 = __ldcs(p + lane + 32);

    #pragma unroll 4
    for (int it = 0; it < 11; ++it) {
        ridx += 64;
        const float4* np = row_ptr(in, b, qy, qx, ridx);
        float4 n0 = __ldcs(np + lane);
        float4 n1 = __ldcs(np + lane + 32);
        bump8(v0, v1, h);
        v0 = n0; v1 = n1;
    }
    bump8(v0, v1, h);
    __syncthreads();

    // Block reduction: 8192 u16 counters -> 32 bin sums (rotated reads).
    unsigned s = 0;
    int base = (tid & 31) * 256 + (tid >> 5) * 32;
    #pragma unroll
    for (int i = 0; i < 32; i++)
        s += hist[base + ((i + tid) & 31)];
    scratch[tid] = s;
    __syncthreads();
    if (tid < 32) {
        unsigned tot = 0;
        #pragma unroll
        for (int c = 0; c < 8; c++)
            tot += scratch[tid + 32 * c];
        atomicAdd(&g_counts[((b << 2) + q) * BINS + tid], tot);
    }

    // Release counts, then bump per-batch arrival counter (32 blocks/batch).
    __threadfence();
    __syncthreads();
    if (tid == 0)
        scratch[256] = atomicAdd(&g_done[b], 1u);
    __syncthreads();
    unsigned rank = scratch[256];
    if (rank != 4 * PARTS - 1) return;      // not the last block of batch b

    // ---- last block of batch b: finalize (overlapped with other batches) ----
    __threadfence();                        // acquire
    __syncthreads();

    float* s1  = (float*)hist;              // [128]: per-quadrant hist / 65536
    float* s0v = ((float*)hist) + 128;      // [32] : full-image hist / 262144

    if (tid < 128) {
        unsigned c = __ldcg(&g_counts[(b << 7) + tid]);
        s1[tid] = (float)c * (1.0f / 65536.0f);
        g_counts[(b << 7) + tid] = 0u;      // reset for next replay
    }
    __syncthreads();
    if (tid < 32)
        s0v[tid] = (s1[tid] + s1[32 + tid] + s1[64 + tid] + s1[96 + tid]) * 0.25f;
    if (tid == 0)
        g_done[b] = 0u;                     // reset for next replay
    __syncthreads();

    #pragma unroll
    for (int k = 0; k < 6; k++) {
        int idx  = tid + 256 * k;           // 0..1535
        int ch   = idx >> 4;
        int cell = idx & 15;                // y*4 + x
        float v = 0.0f;
        if (ch < 32) {
            v = s0v[ch];
        } else if (ch < 64) {
            int qq = ((cell >> 3) << 1) | ((cell >> 1) & 1);  // (y>>1)*2+(x>>1)
            v = s1[qq * BINS + (ch - 32)];
        }
        out[b * 1536 + idx] = v;
    }
}

extern "C" void kernel_launch(void* const* d_in, const int* in_sizes, int n_in,
                              void* d_out, int out_size) {
    (void)in_sizes; (void)n_in; (void)out_size;
    fused_kernel<<<NBLK, 256>>>((const float*)d_in[0], (float*)d_out);
}

// round 11
// speedup vs baseline: 1.0616x; 1.0548x over previous
#include <cuda_runtime.h>

// FeatureExtractor_50165218017745  (R11: R5 champion + prologue overlap)
// Input : imgs_in [64, 3, 512, 512] float32 in [0,1)
// Output: [64, 96, 4, 4] float32
//
// R5 base: parity-packed u16 privatized smem histograms (bank == lane for
// every access -> conflict-free), depth-1 LDG.128 prefetch, 16 KB smem,
// 7 CTAs/SM, 1024 blocks = ONE wave; fused threadfence-reduction epilogue
// finalizes each batch in-overlap and resets scratch for graph replay.
// R11 delta: the first two rows' loads are issued BEFORE the histogram
// zeroing + barrier, hiding the initial DRAM latency under the prologue.

#define BINS   32
#define BATCH  64
#define PARTS  4
#define NBLK   (BATCH * 4 * PARTS)   // 1024 blocks

__device__ unsigned g_counts[BATCH * 4 * BINS];  // zero-init; reset each run
__device__ unsigned g_done[BATCH];               // zero-init; reset each run

// bin = floor(32x) for x in [0,1): FFMA.RZ + 2^23 leaves floor(32x) in the
// low mantissa bits (exact for 0 <= 32x < 2^23).
__device__ __forceinline__ unsigned bin_of(float x) {
    return __float_as_uint(__fmaf_rz(x, 32.0f, 8388608.0f)) & 31u;
}

__device__ __forceinline__ void bump8(const float4& a, const float4& b,
                                      unsigned short* __restrict__ h) {
    h[bin_of(a.x) << 8] += 1u;
    h[bin_of(a.y) << 8] += 1u;
    h[bin_of(a.z) << 8] += 1u;
    h[bin_of(a.w) << 8] += 1u;
    h[bin_of(b.x) << 8] += 1u;
    h[bin_of(b.y) << 8] += 1u;
    h[bin_of(b.z) << 8] += 1u;
    h[bin_of(b.w) << 8] += 1u;
}

__device__ __forceinline__ const float4* row_ptr(const float* __restrict__ in,
                                                 int b, int qy, int qx, int ridx) {
    int c = ridx >> 8;        // channel 0..2
    int r = ridx & 255;       // row within quadrant
    return (const float4*)(in + (((((b * 3 + c) << 9) + (qy << 8) + r) << 9) + (qx << 8)));
}

__global__ __launch_bounds__(256, 7)
void fused_kernel(const float* __restrict__ in, float* __restrict__ out) {
    __shared__ unsigned short hist[BINS * 256];   // 16 KB, parity-packed
    __shared__ unsigned scratch[256 + 1];

    int bid  = blockIdx.x;                  // ((b*4 + q) * PARTS + part)
    int part = bid & (PARTS - 1);
    int q    = (bid >> 2) & 3;
    int b    = bid >> 4;
    int qy   = q >> 1;
    int qx   = q & 1;

    int tid  = threadIdx.x;
    int warp = tid >> 5;
    int lane = tid & 31;

    // Issue the first two rows' loads BEFORE touching smem: their ~600-cycle
    // DRAM latency hides under the zeroing + barrier below.
    int ridx = part * 8 + warp;             // 0..31
    const float4* p0 = row_ptr(in, b, qy, qx, ridx);
    float4 v0 = p0[lane];
    float4 v1 = p0[lane + 32];
    const float4* p1 = row_ptr(in, b, qy, qx, ridx + 32);
    float4 w0 = p1[lane];
    float4 w1 = p1[lane + 32];

    // zero private histograms (4096 u32 words / 256 threads = 4 uint4 each)
    {
        uint4* z = (uint4*)hist;
        #pragma unroll
        for (int i = 0; i < 4; i++)
            z[tid + 256 * i] = make_uint4(0u, 0u, 0u, 0u);
    }
    __syncthreads();

    // Parity-packed slot: byte = bin*512 + (warp>>1)*128 + lane*4 + (warp&1)*2
    // -> bank = lane for every bin; bin b's 256 counters occupy u16 range
    // [b*256, b*256+256) (permuted), so the reduction is layout-agnostic.
    unsigned short* h = hist + ((warp >> 1) << 6) + (lane << 1) + (warp & 1);

    // 768 quadrant-rows (3 ch x 256); 32 warp-stripes -> 24 rows/warp.
    // Steady state identical to R5: depth-1 prefetch.
    #pragma unroll 4
    for (int it = 0; it < 22; ++it) {
        ridx += 32;
        const float4* np = row_ptr(in, b, qy, qx, ridx + 32);
        float4 n0 = np[lane];
        float4 n1 = np[lane + 32];
        bump8(v0, v1, h);
        v0 = w0; v1 = w1;
        w0 = n0; w1 = n1;
    }
    bump8(v0, v1, h);
    bump8(w0, w1, h);
    __syncthreads();

    // Block reduction: 8192 u16 counters -> 32 bin sums (rotated reads).
    unsigned s = 0;
    int base = (tid & 31) * 256 + (tid >> 5) * 32;
    #pragma unroll
    for (int i = 0; i < 32; i++)
        s += hist[base + ((i + tid) & 31)];
    scratch[tid] = s;
    __syncthreads();
    if (tid < 32) {
        unsigned tot = 0;
        #pragma unroll
        for (int c = 0; c < 8; c++)
            tot += scratch[tid + 32 * c];
        atomicAdd(&g_counts[((b << 2) + q) * BINS + tid], tot);
    }

    // Release counts, then bump per-batch arrival counter (16 blocks/batch).
    __threadfence();
    __syncthreads();
    if (tid == 0)
        scratch[256] = atomicAdd(&g_done[b], 1u);
    __syncthreads();
    unsigned rank = scratch[256];
    if (rank != 4 * PARTS - 1) return;      // not the last block of batch b

    // ---- last block of batch b: finalize (overlapped with other batches) ----
    __threadfence();                        // acquire
    __syncthreads();

    float* s1  = (float*)hist;              // [128]: per-quadrant hist / 65536
    float* s0v = ((float*)hist) + 128;      // [32] : full-image hist / 262144

    if (tid < 128) {
        unsigned c = __ldcg(&g_counts[(b << 7) + tid]);
        s1[tid] = (float)c * (1.0f / 65536.0f);
        g_counts[(b << 7) + tid] = 0u;      // reset for next replay
    }
    __syncthreads();
    if (tid < 32)
        s0v[tid] = (s1[tid] + s1[32 + tid] + s1[64 + tid] + s1[96 + tid]) * 0.25f;
    if (tid == 0)
        g_done[b] = 0u;                     // reset for next replay
    __syncthreads();

    #pragma unroll
    for (int k = 0; k < 6; k++) {
        int idx  = tid + 256 * k;           // 0..1535
        int ch   = idx >> 4;
        int cell = idx & 15;                // y*4 + x
        float v = 0.0f;
        if (ch < 32) {
            v = s0v[ch];
        } else if (ch < 64) {
            int qq = ((cell >> 3) << 1) | ((cell >> 1) & 1);  // (y>>1)*2+(x>>1)
            v = s1[qq * BINS + (ch - 32)];
        }
        out[b * 1536 + idx] = v;
    }
}

extern "C" void kernel_launch(void* const* d_in, const int* in_sizes, int n_in,
                              void* d_out, int out_size) {
    (void)in_sizes; (void)n_in; (void)out_size;
    fused_kernel<<<NBLK, 256>>>((const float*)d_in[0], (float*)d_out);
}